// round 6
// baseline (speedup 1.0000x reference)
#include <cuda_runtime.h>
#include <cuda_bf16.h>
#include <cstdint>

// ---------------------------------------------------------------------------
// DNFNetLocalization via mma.sync bf16 GEMM (sm_103 baseline PTX, no 'a' features)
//   dist2[b,f] = dot(A'[b], B'[f]) + c[f],  A'=[x^2, x]  B'=[s^2, -2 s^2 mu]
//   out = softmax_f( exp( sigmoid(T) * exp(-sqrt(dist2)) ) )
// ---------------------------------------------------------------------------

#define BATCH 2048
#define NF    1024
#define DIM   256
#define KK    512        // 2*DIM

__device__ __nv_bfloat16 g_A[BATCH * KK];   // 2 MB
__device__ __nv_bfloat16 g_B[NF * KK];      // 1 MB
__device__ float g_c[NF];

// ===========================================================================
// prep: A-part 4 elems/thread (512 blocks), B-part 8 elems/thread (128 blocks)
// ===========================================================================
union BF4 { __nv_bfloat162 h[2]; uint2 u; };
union BF8 { __nv_bfloat162 h[4]; uint4 u; };

__global__ __launch_bounds__(256)
void prep_kernel(const float* __restrict__ x,
                 const float* __restrict__ mu,
                 const float* __restrict__ sigma) {
    const int blk = blockIdx.x;
    if (blk < 512) {
        // ---- A part: 4 elems/thread ----
        const int vid = blk * 256 + threadIdx.x;     // 0..131071
        const int row = vid >> 6;                    // 0..2047 (64 thr/row)
        const int d0  = (vid & 63) * 4;              // 0..252
        const float4 v = *reinterpret_cast<const float4*>(x + row * DIM + d0);

        BF4 sq, ln;
        sq.h[0] = __floats2bfloat162_rn(v.x * v.x, v.y * v.y);
        sq.h[1] = __floats2bfloat162_rn(v.z * v.z, v.w * v.w);
        ln.h[0] = __floats2bfloat162_rn(v.x, v.y);
        ln.h[1] = __floats2bfloat162_rn(v.z, v.w);

        *reinterpret_cast<uint2*>(g_A + row * KK + d0)       = sq.u;
        *reinterpret_cast<uint2*>(g_A + row * KK + DIM + d0) = ln.u;
    } else {
        // ---- B part: 8 elems/thread, warp-per-row shuffle reduce ----
        const int vid = (blk - 512) * 256 + threadIdx.x;   // 0..32767
        const int row = vid >> 5;                          // 0..1023
        const int d0  = (vid & 31) * 8;
        const float4 s0 = *reinterpret_cast<const float4*>(sigma + row * DIM + d0);
        const float4 s1 = *reinterpret_cast<const float4*>(sigma + row * DIM + d0 + 4);
        const float4 m0 = *reinterpret_cast<const float4*>(mu + row * DIM + d0);
        const float4 m1 = *reinterpret_cast<const float4*>(mu + row * DIM + d0 + 4);

        const float w0 = s0.x * s0.x, w1 = s0.y * s0.y, w2 = s0.z * s0.z, w3 = s0.w * s0.w;
        const float w4 = s1.x * s1.x, w5 = s1.y * s1.y, w6 = s1.z * s1.z, w7 = s1.w * s1.w;

        BF8 wv, bv;
        wv.h[0] = __floats2bfloat162_rn(w0, w1);
        wv.h[1] = __floats2bfloat162_rn(w2, w3);
        wv.h[2] = __floats2bfloat162_rn(w4, w5);
        wv.h[3] = __floats2bfloat162_rn(w6, w7);
        bv.h[0] = __floats2bfloat162_rn(-2.0f * w0 * m0.x, -2.0f * w1 * m0.y);
        bv.h[1] = __floats2bfloat162_rn(-2.0f * w2 * m0.z, -2.0f * w3 * m0.w);
        bv.h[2] = __floats2bfloat162_rn(-2.0f * w4 * m1.x, -2.0f * w5 * m1.y);
        bv.h[3] = __floats2bfloat162_rn(-2.0f * w6 * m1.z, -2.0f * w7 * m1.w);

        *reinterpret_cast<uint4*>(g_B + row * KK + d0)       = wv.u;
        *reinterpret_cast<uint4*>(g_B + row * KK + DIM + d0) = bv.u;

        float r = w0 * m0.x * m0.x + w1 * m0.y * m0.y
                + w2 * m0.z * m0.z + w3 * m0.w * m0.w
                + w4 * m1.x * m1.x + w5 * m1.y * m1.y
                + w6 * m1.z * m1.z + w7 * m1.w * m1.w;
        #pragma unroll
        for (int off = 16; off > 0; off >>= 1)
            r += __shfl_xor_sync(0xFFFFFFFFu, r, off);
        if ((threadIdx.x & 31) == 0) g_c[row] = r;
    }
}

// ===========================================================================
// mma.sync GEMM (BM=128, BN=128, BK=64, 8 warps, warp tile 64x32)
// 3-stage cp.async software pipeline, 110.6 KB dynamic smem
// ===========================================================================
#define BM 128
#define BN 128
#define BK 64
#define PITCH 72            // halves per smem row (64 + 8 pad); 144B
#define NCHUNK (KK / BK)    // 8
#define NSTAGE 3
#define TILE_H (BM * PITCH)                 // halves per tile-stage (9216)
#define SMEM_DYN (2 * NSTAGE * TILE_H * 2)  // bytes (110592)

__device__ __forceinline__ uint32_t smem_addr_u32(const void* p) {
    return (uint32_t)__cvta_generic_to_shared(p);
}

#define CP_ASYNC16(saddr, gptr) \
    asm volatile("cp.async.cg.shared.global [%0], [%1], 16;" \
                 :: "r"(saddr), "l"(gptr))
#define CP_COMMIT() asm volatile("cp.async.commit_group;")
#define CP_WAIT(n)  asm volatile("cp.async.wait_group %0;" :: "n"(n) : "memory")

#define LDMATRIX_X4(r0, r1, r2, r3, addr) \
    asm volatile("ldmatrix.sync.aligned.m8n8.x4.shared.b16 {%0,%1,%2,%3}, [%4];" \
                 : "=r"(r0), "=r"(r1), "=r"(r2), "=r"(r3) : "r"(addr))

#define MMA_BF16(c0, c1, c2, c3, a0, a1, a2, a3, b0, b1) \
    asm volatile("mma.sync.aligned.m16n8k16.row.col.f32.bf16.bf16.f32 " \
                 "{%0,%1,%2,%3}, {%4,%5,%6,%7}, {%8,%9}, {%0,%1,%2,%3};" \
                 : "+f"(c0), "+f"(c1), "+f"(c2), "+f"(c3) \
                 : "r"(a0), "r"(a1), "r"(a2), "r"(a3), "r"(b0), "r"(b1))

__device__ __forceinline__ float fsqrt_approx(float x) {
    float r;
    asm("sqrt.approx.f32 %0, %1;" : "=f"(r) : "f"(x));
    return r;
}

__global__ __launch_bounds__(256, 1)
void gemm_mma_kernel(const float* __restrict__ tptr, float* __restrict__ out) {
    extern __shared__ __nv_bfloat16 smem[];
    __nv_bfloat16* const As = smem;                       // NSTAGE * TILE_H
    __nv_bfloat16* const Bs = smem + NSTAGE * TILE_H;     // NSTAGE * TILE_H

    const int tid  = threadIdx.x;
    const int wid  = tid >> 5;
    const int lane = tid & 31;
    const int bN   = blockIdx.x * BN;
    const int bM   = blockIdx.y * BM;

    const int warpM = wid & 1;        // 0..1  -> 64 rows
    const int warpN = wid >> 1;       // 0..3  -> 32 cols

    const __nv_bfloat16* Agp = g_A + (size_t)bM * KK;
    const __nv_bfloat16* Bgp = g_B + (size_t)bN * KK;

    // per-thread load mapping: 4 x 16B vectors per matrix per chunk
    // chunk = 128 rows x 64 halves (128B) = 1024 vectors; vid = tid + i*256
    const int ld_row = tid >> 3;            // 0..31 (4 row groups of 32)
    const int ld_v   = tid & 7;             // 16B slot within 128B row chunk

    auto load_chunk = [&](int kc, int slot) {
        __nv_bfloat16* a = As + slot * TILE_H;
        __nv_bfloat16* b = Bs + slot * TILE_H;
        #pragma unroll
        for (int i = 0; i < 4; ++i) {
            int row = ld_row + i * 32;
            uint32_t sa = smem_addr_u32(a + row * PITCH + ld_v * 8);
            uint32_t sb = smem_addr_u32(b + row * PITCH + ld_v * 8);
            const __nv_bfloat16* ga = Agp + (size_t)row * KK + kc * BK + ld_v * 8;
            const __nv_bfloat16* gb = Bgp + (size_t)row * KK + kc * BK + ld_v * 8;
            CP_ASYNC16(sa, ga);
            CP_ASYNC16(sb, gb);
        }
        CP_COMMIT();
    };

    // ---- ldmatrix address components ----
    const int a_row  = lane & 15;
    const int a_koff = (lane >> 4) << 3;
    const int b_nrow = (lane & 7) + ((lane >> 4) << 3);
    const int b_koff = ((lane >> 3) & 1) << 3;

    float acc[4][4][4];
    #pragma unroll
    for (int m = 0; m < 4; ++m)
        #pragma unroll
        for (int n = 0; n < 4; ++n)
            #pragma unroll
            for (int j = 0; j < 4; ++j) acc[m][n][j] = 0.0f;

    load_chunk(0, 0);
    load_chunk(1, 1);

    for (int kc = 0; kc < NCHUNK; ++kc) {
        if (kc == NCHUNK - 1) { CP_WAIT(0); } else { CP_WAIT(1); }
        __syncthreads();

        if (kc + 2 < NCHUNK) load_chunk(kc + 2, (kc + 2) % NSTAGE);

        const __nv_bfloat16* at = As + (kc % NSTAGE) * TILE_H;
        const __nv_bfloat16* bt = Bs + (kc % NSTAGE) * TILE_H;

        #pragma unroll
        for (int ks = 0; ks < 4; ++ks) {             // four k16 steps per chunk
            const int k0 = ks * 16;

            uint32_t af[4][4];
            #pragma unroll
            for (int mt = 0; mt < 4; ++mt) {
                uint32_t addr = smem_addr_u32(
                    at + (warpM * 64 + mt * 16 + a_row) * PITCH + k0 + a_koff);
                LDMATRIX_X4(af[mt][0], af[mt][1], af[mt][2], af[mt][3], addr);
            }

            uint32_t bf[4][2];
            #pragma unroll
            for (int np = 0; np < 2; ++np) {         // each x4 covers 2 n-tiles
                uint32_t addr = smem_addr_u32(
                    bt + (warpN * 32 + np * 16 + b_nrow) * PITCH + k0 + b_koff);
                LDMATRIX_X4(bf[np * 2][0], bf[np * 2][1],
                            bf[np * 2 + 1][0], bf[np * 2 + 1][1], addr);
            }

            #pragma unroll
            for (int mt = 0; mt < 4; ++mt)
                #pragma unroll
                for (int nt = 0; nt < 4; ++nt)
                    MMA_BF16(acc[mt][nt][0], acc[mt][nt][1],
                             acc[mt][nt][2], acc[mt][nt][3],
                             af[mt][0], af[mt][1], af[mt][2], af[mt][3],
                             bf[nt][0], bf[nt][1]);
        }
    }

    // ------------------- fused epilogue -------------------
    const float t    = *tptr;
    const float sigT = 1.0f / (1.0f + __expf(-t));

    const int g  = lane >> 2;       // 0..7
    const int tq = lane & 3;        // 0..3

    float2 cpair[4];
    #pragma unroll
    for (int nt = 0; nt < 4; ++nt) {
        int col = bN + warpN * 32 + nt * 8 + 2 * tq;
        cpair[nt] = *reinterpret_cast<const float2*>(&g_c[col]);
    }

    #pragma unroll
    for (int mt = 0; mt < 4; ++mt) {
        const int r0 = bM + warpM * 64 + mt * 16 + g;
        #pragma unroll
        for (int nt = 0; nt < 4; ++nt) {
            const int col = bN + warpN * 32 + nt * 8 + 2 * tq;
            float2 o0, o1;
            {
                float d2 = fmaxf(acc[mt][nt][0] + cpair[nt].x, 0.0f);
                o0.x = __expf(sigT * __expf(-fsqrt_approx(d2)));
                d2 = fmaxf(acc[mt][nt][1] + cpair[nt].y, 0.0f);
                o0.y = __expf(sigT * __expf(-fsqrt_approx(d2)));
                d2 = fmaxf(acc[mt][nt][2] + cpair[nt].x, 0.0f);
                o1.x = __expf(sigT * __expf(-fsqrt_approx(d2)));
                d2 = fmaxf(acc[mt][nt][3] + cpair[nt].y, 0.0f);
                o1.y = __expf(sigT * __expf(-fsqrt_approx(d2)));
            }
            *reinterpret_cast<float2*>(&out[(size_t)r0 * NF + col])       = o0;
            *reinterpret_cast<float2*>(&out[(size_t)(r0 + 8) * NF + col]) = o1;
        }
    }
}

// ===========================================================================
// normalize: one block (128 threads) per row
// ===========================================================================
__global__ __launch_bounds__(128)
void normalize_kernel(float* __restrict__ out) {
    const int b    = blockIdx.x;        // 0..2047
    const int tid  = threadIdx.x;       // 0..127
    const int lane = tid & 31;
    const int w    = tid >> 5;
    float* rp = out + (size_t)b * NF;

    float4 v0 = *reinterpret_cast<float4*>(rp + tid * 4);
    float4 v1 = *reinterpret_cast<float4*>(rp + 512 + tid * 4);
    float s = (v0.x + v0.y) + (v0.z + v0.w) + (v1.x + v1.y) + (v1.z + v1.w);

    #pragma unroll
    for (int off = 16; off > 0; off >>= 1)
        s += __shfl_xor_sync(0xFFFFFFFFu, s, off);

    __shared__ float ws[4];
    if (lane == 0) ws[w] = s;
    __syncthreads();
    const float tot = (ws[0] + ws[1]) + (ws[2] + ws[3]);
    const float inv = 1.0f / tot;

    v0.x *= inv; v0.y *= inv; v0.z *= inv; v0.w *= inv;
    v1.x *= inv; v1.y *= inv; v1.z *= inv; v1.w *= inv;
    *reinterpret_cast<float4*>(rp + tid * 4)       = v0;
    *reinterpret_cast<float4*>(rp + 512 + tid * 4) = v1;
}

// ===========================================================================
extern "C" void kernel_launch(void* const* d_in, const int* in_sizes, int n_in,
                              void* d_out, int out_size) {
    const float* x     = (const float*)d_in[0];   // (2048, 256)
    const float* mu    = (const float*)d_in[1];   // (1024, 256)
    const float* sigma = (const float*)d_in[2];   // (1, 1024, 256)
    const float* temp  = (const float*)d_in[3];   // scalar
    float* out = (float*)d_out;                   // (2048, 1024)

    cudaFuncSetAttribute(gemm_mma_kernel,
                         cudaFuncAttributeMaxDynamicSharedMemorySize, SMEM_DYN);

    prep_kernel<<<640, 256>>>(x, mu, sigma);
    gemm_mma_kernel<<<dim3(NF / BN, BATCH / BM), 256, SMEM_DYN>>>(temp, out);
    normalize_kernel<<<BATCH, 128>>>(out);
}

// round 7
// speedup vs baseline: 1.1064x; 1.1064x over previous
#include <cuda_runtime.h>
#include <cuda_bf16.h>
#include <cstdint>

// ---------------------------------------------------------------------------
// DNFNetLocalization, fused prep + mma.sync bf16 GEMM + softmax normalize
//   dist2[b,f] = dot(A'[b], B'[f]) + c[f],  A'=[x^2, x]  B'=[s^2, -2 s^2 mu]
//   out = softmax_f( exp( sigmoid(T) * exp(-sqrt(dist2)) ) )
// ---------------------------------------------------------------------------

#define BATCH 2048
#define NF    1024
#define DIM   256
#define KK    512        // 2*DIM

__device__ __nv_bfloat16 g_A[BATCH * KK];   // 2 MB
__device__ __nv_bfloat16 g_B[NF * KK];      // 1 MB
__device__ float g_c[NF];
__device__ int   g_sync = 0;                // grid barrier; reset by normalize

#define GRID_CTAS 128

union BF8 { __nv_bfloat162 h[4]; uint4 u; };

// ===========================================================================
// mma.sync GEMM (BM=128, BN=128, BK=32, 8 warps, warp tile 64x32)
// 3-stage cp.async pipeline; prep fused as prologue + device grid-sync
// ===========================================================================
#define BM 128
#define BN 128
#define BK 32
#define PITCH 40            // halves per smem row (32 + 8 pad)
#define NCHUNK (KK / BK)    // 16
#define NSTAGE 3
#define TILE_H (BM * PITCH)                 // 5120 halves per tile-stage
#define SMEM_DYN (2 * NSTAGE * TILE_H * 2)  // 61440 bytes

__device__ __forceinline__ uint32_t smem_addr_u32(const void* p) {
    return (uint32_t)__cvta_generic_to_shared(p);
}

#define CP_ASYNC16(saddr, gptr) \
    asm volatile("cp.async.cg.shared.global [%0], [%1], 16;" \
                 :: "r"(saddr), "l"(gptr))
#define CP_COMMIT() asm volatile("cp.async.commit_group;")
#define CP_WAIT(n)  asm volatile("cp.async.wait_group %0;" :: "n"(n) : "memory")

#define LDMATRIX_X4(r0, r1, r2, r3, addr) \
    asm volatile("ldmatrix.sync.aligned.m8n8.x4.shared.b16 {%0,%1,%2,%3}, [%4];" \
                 : "=r"(r0), "=r"(r1), "=r"(r2), "=r"(r3) : "r"(addr))

#define MMA_BF16(c0, c1, c2, c3, a0, a1, a2, a3, b0, b1) \
    asm volatile("mma.sync.aligned.m16n8k16.row.col.f32.bf16.bf16.f32 " \
                 "{%0,%1,%2,%3}, {%4,%5,%6,%7}, {%8,%9}, {%0,%1,%2,%3};" \
                 : "+f"(c0), "+f"(c1), "+f"(c2), "+f"(c3) \
                 : "r"(a0), "r"(a1), "r"(a2), "r"(a3), "r"(b0), "r"(b1))

__device__ __forceinline__ float fsqrt_approx(float x) {
    float r;
    asm("sqrt.approx.f32 %0, %1;" : "=f"(r) : "f"(x));
    return r;
}

__global__ __launch_bounds__(256, 1)
void gemm_fused_kernel(const float* __restrict__ x,
                       const float* __restrict__ mu,
                       const float* __restrict__ sigma,
                       const float* __restrict__ tptr,
                       float* __restrict__ out) {
    extern __shared__ __nv_bfloat16 smem[];
    __nv_bfloat16* const As = smem;
    __nv_bfloat16* const Bs = smem + NSTAGE * TILE_H;

    const int tid  = threadIdx.x;
    const int wid  = tid >> 5;
    const int lane = tid & 31;
    const int bN   = blockIdx.x * BN;
    const int bM   = blockIdx.y * BM;
    const int bid  = blockIdx.y * (NF / BN) + blockIdx.x;   // 0..127

    // =============== fused prep prologue ===============
    {
        // ---- A part: rows [bid*16, bid*16+16), 16 thr/row, 16 elems/thr ----
        const int arow = bid * 16 + (tid >> 4);
        const int ad0  = (tid & 15) * 16;
        const float* xr = x + arow * DIM + ad0;
        float4 v0 = *reinterpret_cast<const float4*>(xr);
        float4 v1 = *reinterpret_cast<const float4*>(xr + 4);
        float4 v2 = *reinterpret_cast<const float4*>(xr + 8);
        float4 v3 = *reinterpret_cast<const float4*>(xr + 12);

        BF8 sq0, sq1, ln0, ln1;
        sq0.h[0] = __floats2bfloat162_rn(v0.x * v0.x, v0.y * v0.y);
        sq0.h[1] = __floats2bfloat162_rn(v0.z * v0.z, v0.w * v0.w);
        sq0.h[2] = __floats2bfloat162_rn(v1.x * v1.x, v1.y * v1.y);
        sq0.h[3] = __floats2bfloat162_rn(v1.z * v1.z, v1.w * v1.w);
        sq1.h[0] = __floats2bfloat162_rn(v2.x * v2.x, v2.y * v2.y);
        sq1.h[1] = __floats2bfloat162_rn(v2.z * v2.z, v2.w * v2.w);
        sq1.h[2] = __floats2bfloat162_rn(v3.x * v3.x, v3.y * v3.y);
        sq1.h[3] = __floats2bfloat162_rn(v3.z * v3.z, v3.w * v3.w);
        ln0.h[0] = __floats2bfloat162_rn(v0.x, v0.y);
        ln0.h[1] = __floats2bfloat162_rn(v0.z, v0.w);
        ln0.h[2] = __floats2bfloat162_rn(v1.x, v1.y);
        ln0.h[3] = __floats2bfloat162_rn(v1.z, v1.w);
        ln1.h[0] = __floats2bfloat162_rn(v2.x, v2.y);
        ln1.h[1] = __floats2bfloat162_rn(v2.z, v2.w);
        ln1.h[2] = __floats2bfloat162_rn(v3.x, v3.y);
        ln1.h[3] = __floats2bfloat162_rn(v3.z, v3.w);

        *reinterpret_cast<uint4*>(g_A + arow * KK + ad0)           = sq0.u;
        *reinterpret_cast<uint4*>(g_A + arow * KK + ad0 + 8)       = sq1.u;
        *reinterpret_cast<uint4*>(g_A + arow * KK + DIM + ad0)     = ln0.u;
        *reinterpret_cast<uint4*>(g_A + arow * KK + DIM + ad0 + 8) = ln1.u;

        // ---- B part: rows [bid*8, bid*8+8), warp w -> row w, 8 elems/lane ----
        const int brow = bid * 8 + wid;
        const int bd0  = lane * 8;
        const float4 s0 = *reinterpret_cast<const float4*>(sigma + brow * DIM + bd0);
        const float4 s1 = *reinterpret_cast<const float4*>(sigma + brow * DIM + bd0 + 4);
        const float4 m0 = *reinterpret_cast<const float4*>(mu + brow * DIM + bd0);
        const float4 m1 = *reinterpret_cast<const float4*>(mu + brow * DIM + bd0 + 4);

        const float w0 = s0.x * s0.x, w1 = s0.y * s0.y, w2 = s0.z * s0.z, w3 = s0.w * s0.w;
        const float w4 = s1.x * s1.x, w5 = s1.y * s1.y, w6 = s1.z * s1.z, w7 = s1.w * s1.w;

        BF8 wv, bv;
        wv.h[0] = __floats2bfloat162_rn(w0, w1);
        wv.h[1] = __floats2bfloat162_rn(w2, w3);
        wv.h[2] = __floats2bfloat162_rn(w4, w5);
        wv.h[3] = __floats2bfloat162_rn(w6, w7);
        bv.h[0] = __floats2bfloat162_rn(-2.0f * w0 * m0.x, -2.0f * w1 * m0.y);
        bv.h[1] = __floats2bfloat162_rn(-2.0f * w2 * m0.z, -2.0f * w3 * m0.w);
        bv.h[2] = __floats2bfloat162_rn(-2.0f * w4 * m1.x, -2.0f * w5 * m1.y);
        bv.h[3] = __floats2bfloat162_rn(-2.0f * w6 * m1.z, -2.0f * w7 * m1.w);

        *reinterpret_cast<uint4*>(g_B + brow * KK + bd0)       = wv.u;
        *reinterpret_cast<uint4*>(g_B + brow * KK + DIM + bd0) = bv.u;

        float r = w0 * m0.x * m0.x + w1 * m0.y * m0.y
                + w2 * m0.z * m0.z + w3 * m0.w * m0.w
                + w4 * m1.x * m1.x + w5 * m1.y * m1.y
                + w6 * m1.z * m1.z + w7 * m1.w * m1.w;
        #pragma unroll
        for (int off = 16; off > 0; off >>= 1)
            r += __shfl_xor_sync(0xFFFFFFFFu, r, off);
        if (lane == 0) g_c[brow] = r;
    }

    // =============== device grid sync (all 128 CTAs resident: grid <= 148) ===
    __syncthreads();
    if (tid == 0) {
        __threadfence();
        atomicAdd(&g_sync, 1);
        int v;
        do {
            asm volatile("ld.global.acquire.gpu.b32 %0, [%1];"
                         : "=r"(v) : "l"(&g_sync));
        } while (v < GRID_CTAS);
    }
    __syncthreads();

    // =============== GEMM mainloop ===============
    const int warpM = wid & 1;        // 0..1  -> 64 rows
    const int warpN = wid >> 1;       // 0..3  -> 32 cols

    const __nv_bfloat16* Agp = g_A + (size_t)bM * KK;
    const __nv_bfloat16* Bgp = g_B + (size_t)bN * KK;

    const int ld_row = tid >> 2;            // 0..63 (two row groups)
    const int ld_v   = tid & 3;             // 16B slot within 64B row chunk

    auto load_chunk = [&](int kc, int slot) {
        __nv_bfloat16* a = As + slot * TILE_H;
        __nv_bfloat16* b = Bs + slot * TILE_H;
        #pragma unroll
        for (int i = 0; i < 2; ++i) {
            int row = ld_row + i * 64;
            uint32_t sa = smem_addr_u32(a + row * PITCH + ld_v * 8);
            uint32_t sb = smem_addr_u32(b + row * PITCH + ld_v * 8);
            const __nv_bfloat16* ga = Agp + (size_t)row * KK + kc * BK + ld_v * 8;
            const __nv_bfloat16* gb = Bgp + (size_t)row * KK + kc * BK + ld_v * 8;
            CP_ASYNC16(sa, ga);
            CP_ASYNC16(sb, gb);
        }
        CP_COMMIT();
    };

    const int a_row  = lane & 15;
    const int a_koff = (lane >> 4) << 3;
    const int b_nrow = (lane & 7) + ((lane >> 4) << 3);
    const int b_koff = ((lane >> 3) & 1) << 3;

    float acc[4][4][4];
    #pragma unroll
    for (int m = 0; m < 4; ++m)
        #pragma unroll
        for (int n = 0; n < 4; ++n)
            #pragma unroll
            for (int j = 0; j < 4; ++j) acc[m][n][j] = 0.0f;

    load_chunk(0, 0);
    load_chunk(1, 1);

    for (int kc = 0; kc < NCHUNK; ++kc) {
        if (kc == NCHUNK - 1) { CP_WAIT(0); } else { CP_WAIT(1); }
        __syncthreads();

        if (kc + 2 < NCHUNK) load_chunk(kc + 2, (kc + 2) % NSTAGE);

        const __nv_bfloat16* at = As + (kc % NSTAGE) * TILE_H;
        const __nv_bfloat16* bt = Bs + (kc % NSTAGE) * TILE_H;

        #pragma unroll
        for (int ks = 0; ks < 2; ++ks) {
            const int k0 = ks * 16;

            uint32_t af[4][4];
            #pragma unroll
            for (int mt = 0; mt < 4; ++mt) {
                uint32_t addr = smem_addr_u32(
                    at + (warpM * 64 + mt * 16 + a_row) * PITCH + k0 + a_koff);
                LDMATRIX_X4(af[mt][0], af[mt][1], af[mt][2], af[mt][3], addr);
            }

            uint32_t bf[4][2];
            #pragma unroll
            for (int np = 0; np < 2; ++np) {
                uint32_t addr = smem_addr_u32(
                    bt + (warpN * 32 + np * 16 + b_nrow) * PITCH + k0 + b_koff);
                LDMATRIX_X4(bf[np * 2][0], bf[np * 2][1],
                            bf[np * 2 + 1][0], bf[np * 2 + 1][1], addr);
            }

            #pragma unroll
            for (int mt = 0; mt < 4; ++mt)
                #pragma unroll
                for (int nt = 0; nt < 4; ++nt)
                    MMA_BF16(acc[mt][nt][0], acc[mt][nt][1],
                             acc[mt][nt][2], acc[mt][nt][3],
                             af[mt][0], af[mt][1], af[mt][2], af[mt][3],
                             bf[nt][0], bf[nt][1]);
        }
    }

    // =============== fused epilogue ===============
    const float t    = *tptr;
    const float sigT = 1.0f / (1.0f + __expf(-t));

    const int g  = lane >> 2;
    const int tq = lane & 3;

    float2 cpair[4];
    #pragma unroll
    for (int nt = 0; nt < 4; ++nt) {
        int col = bN + warpN * 32 + nt * 8 + 2 * tq;
        cpair[nt] = *reinterpret_cast<const float2*>(&g_c[col]);
    }

    #pragma unroll
    for (int mt = 0; mt < 4; ++mt) {
        const int r0 = bM + warpM * 64 + mt * 16 + g;
        #pragma unroll
        for (int nt = 0; nt < 4; ++nt) {
            const int col = bN + warpN * 32 + nt * 8 + 2 * tq;
            float2 o0, o1;
            {
                float d2 = fmaxf(acc[mt][nt][0] + cpair[nt].x, 0.0f);
                o0.x = __expf(sigT * __expf(-fsqrt_approx(d2)));
                d2 = fmaxf(acc[mt][nt][1] + cpair[nt].y, 0.0f);
                o0.y = __expf(sigT * __expf(-fsqrt_approx(d2)));
                d2 = fmaxf(acc[mt][nt][2] + cpair[nt].x, 0.0f);
                o1.x = __expf(sigT * __expf(-fsqrt_approx(d2)));
                d2 = fmaxf(acc[mt][nt][3] + cpair[nt].y, 0.0f);
                o1.y = __expf(sigT * __expf(-fsqrt_approx(d2)));
            }
            *reinterpret_cast<float2*>(&out[(size_t)r0 * NF + col])       = o0;
            *reinterpret_cast<float2*>(&out[(size_t)(r0 + 8) * NF + col]) = o1;
        }
    }
}

// ===========================================================================
// normalize: one block (128 threads) per row; also resets the grid barrier
// ===========================================================================
__global__ __launch_bounds__(128)
void normalize_kernel(float* __restrict__ out) {
    const int b    = blockIdx.x;
    const int tid  = threadIdx.x;
    const int lane = tid & 31;
    const int w    = tid >> 5;

    if (b == 0 && tid == 0) g_sync = 0;   // reset barrier for next replay

    float* rp = out + (size_t)b * NF;

    float4 v0 = *reinterpret_cast<float4*>(rp + tid * 4);
    float4 v1 = *reinterpret_cast<float4*>(rp + 512 + tid * 4);
    float s = (v0.x + v0.y) + (v0.z + v0.w) + (v1.x + v1.y) + (v1.z + v1.w);

    #pragma unroll
    for (int off = 16; off > 0; off >>= 1)
        s += __shfl_xor_sync(0xFFFFFFFFu, s, off);

    __shared__ float ws[4];
    if (lane == 0) ws[w] = s;
    __syncthreads();
    const float tot = (ws[0] + ws[1]) + (ws[2] + ws[3]);
    const float inv = 1.0f / tot;

    v0.x *= inv; v0.y *= inv; v0.z *= inv; v0.w *= inv;
    v1.x *= inv; v1.y *= inv; v1.z *= inv; v1.w *= inv;
    *reinterpret_cast<float4*>(rp + tid * 4)       = v0;
    *reinterpret_cast<float4*>(rp + 512 + tid * 4) = v1;
}

// ===========================================================================
extern "C" void kernel_launch(void* const* d_in, const int* in_sizes, int n_in,
                              void* d_out, int out_size) {
    const float* x     = (const float*)d_in[0];   // (2048, 256)
    const float* mu    = (const float*)d_in[1];   // (1024, 256)
    const float* sigma = (const float*)d_in[2];   // (1, 1024, 256)
    const float* temp  = (const float*)d_in[3];   // scalar
    float* out = (float*)d_out;                   // (2048, 1024)

    cudaFuncSetAttribute(gemm_fused_kernel,
                         cudaFuncAttributeMaxDynamicSharedMemorySize, SMEM_DYN);

    gemm_fused_kernel<<<dim3(NF / BN, BATCH / BM), 256, SMEM_DYN>>>(
        x, mu, sigma, temp, out);
    normalize_kernel<<<BATCH, 128>>>(out);
}